// round 2
// baseline (speedup 1.0000x reference)
#include <cuda_runtime.h>
#include <math.h>

// Problem constants
#define BB 4
#define SS 4096
#define EE 1024
#define HH 128
#define CC 128          // chunk size
#define NCHUNK (SS/CC)  // 32
#define LG2G  (-0.04580368938794f)   // log2(0.96875)
#define LOG2_10000 13.287712379549449

// -------- scratch (device globals; no allocations allowed) --------
__device__ float g_Q[BB*SS*HH];                 // 8 MB
__device__ float g_K[BB*SS*HH];                 // 8 MB
__device__ float g_V[BB*SS*HH];                 // 8 MB
__device__ float g_A[BB*NCHUNK*HH*HH];          // 8 MB  per-chunk K^T diag(gamma) V
__device__ float g_St[BB*NCHUNK*HH*HH];         // 8 MB  prefix states

// ====================================================================
// Kernel 1: fused projection GEMM + xpos rotary.
//   P = X @ W^T + b   (M=B*S=16384, N=H=128, K=E=1024)
//   z = 0: Q (xpos up), 1: K (xpos down), 2: V (plain)
// Tile: BM=64, BN=128, BK=16; 256 threads; 4x8 per-thread microtile.
// ====================================================================
#define BM 64
#define BN 128
#define BKK 16

__global__ void proj_xpos_kernel(const float* __restrict__ q,
                                 const float* __restrict__ k,
                                 const float* __restrict__ v,
                                 const float* __restrict__ Wq, const float* __restrict__ bq,
                                 const float* __restrict__ Wk, const float* __restrict__ bk,
                                 const float* __restrict__ Wv, const float* __restrict__ bv)
{
    int z = blockIdx.z;
    const float* X   = (z == 0) ? q  : (z == 1) ? k  : v;
    const float* W   = (z == 0) ? Wq : (z == 1) ? Wk : Wv;
    const float* bia = (z == 0) ? bq : (z == 1) ? bk : bv;
    float* OUT       = (z == 0) ? g_Q : (z == 1) ? g_K : g_V;

    __shared__ float As[BKK][BM + 4];   // transposed A tile
    __shared__ float Bs[BKK][BN + 4];   // W^T tile

    const int tid = threadIdx.x;
    const int tx  = tid & 15;
    const int ty  = tid >> 4;
    const int rowBase = ty * 4;
    const int colBase = tx * 8;
    const int m0 = blockIdx.x * BM;

    float acc[4][8];
    #pragma unroll
    for (int r = 0; r < 4; r++)
        #pragma unroll
        for (int c = 0; c < 8; c++) acc[r][c] = 0.f;

    for (int k0 = 0; k0 < EE; k0 += BKK) {
        // load A tile: 64x16, transposed into As[kk][row]
        #pragma unroll
        for (int i = 0; i < 4; i++) {
            int idx = i * 256 + tid;
            int r  = idx >> 4;
            int kk = idx & 15;
            As[kk][r] = X[(size_t)(m0 + r) * EE + k0 + kk];
        }
        // load B tile: Bs[kk][n] = W[n][k0+kk]
        #pragma unroll
        for (int i = 0; i < 8; i++) {
            int idx = i * 256 + tid;
            int n  = idx >> 4;
            int kk = idx & 15;
            Bs[kk][n] = W[(size_t)n * EE + k0 + kk];
        }
        __syncthreads();
        #pragma unroll
        for (int kk = 0; kk < BKK; kk++) {
            float4 a4 = *(const float4*)&As[kk][rowBase];
            float4 b0 = *(const float4*)&Bs[kk][colBase];
            float4 b1 = *(const float4*)&Bs[kk][colBase + 4];
            float a[4] = {a4.x, a4.y, a4.z, a4.w};
            float bb[8] = {b0.x, b0.y, b0.z, b0.w, b1.x, b1.y, b1.z, b1.w};
            #pragma unroll
            for (int r = 0; r < 4; r++)
                #pragma unroll
                for (int c = 0; c < 8; c++)
                    acc[r][c] = fmaf(a[r], bb[c], acc[r][c]);
        }
        __syncthreads();
    }

    // epilogue: +bias, then xpos for z<2
    #pragma unroll
    for (int r = 0; r < 4; r++) {
        int gm = m0 + rowBase + r;
        int s  = gm & (SS - 1);
        float* orow = OUT + (size_t)gm * HH;
        if (z == 2) {
            #pragma unroll
            for (int c = 0; c < 8; c++)
                orow[colBase + c] = acc[r][c] + bia[colBase + c];
        } else {
            float ps = (float)s;
            #pragma unroll
            for (int c = 0; c < 8; c += 2) {
                int h = colBase + c;
                int d = h >> 1;
                float x0 = acc[r][c]     + bia[h];
                float x1 = acc[r][c + 1] + bia[h + 1];
                float sv = (2.0f * (float)d + 51.2f) * (1.0f / 179.2f);
                float scale = powf(sv, ps * (1.0f / 512.0f));
                if (z == 1) scale = 1.0f / scale;
                float invf = (float)exp2(-(double)d * (LOG2_10000 / 64.0));
                float sn, cs;
                sincosf(ps * invf, &sn, &cs);
                sn *= scale; cs *= scale;
                orow[h]     = x0 * cs - x1 * sn;
                orow[h + 1] = x1 * cs + x0 * sn;
            }
        }
    }
}

// ====================================================================
// Kernel 2: per-chunk summaries A_c[h1,h2] = sum_j gamma^(C-1-j) K[j,h1] V[j,h2]
// ====================================================================
__global__ void chunk_kv_kernel()
{
    int bc = blockIdx.x;
    int b = bc >> 5;
    int c = bc & 31;
    const float* Kp = g_K + (size_t)(b * SS + c * CC) * HH;
    const float* Vp = g_V + (size_t)(b * SS + c * CC) * HH;
    float* Ap = g_A + (size_t)bc * HH * HH;

    __shared__ float Ks[16][HH + 4];
    __shared__ float Vs[16][HH + 4];

    const int tid = threadIdx.x;
    const int tx = tid & 15, ty = tid >> 4;
    const int h1b = ty * 8, h2b = tx * 8;

    float acc[8][8];
    #pragma unroll
    for (int r = 0; r < 8; r++)
        #pragma unroll
        for (int cc2 = 0; cc2 < 8; cc2++) acc[r][cc2] = 0.f;

    for (int j0 = 0; j0 < CC; j0 += 16) {
        #pragma unroll
        for (int i = 0; i < 8; i++) {
            int idx = i * 256 + tid;
            int j = idx >> 7;
            int h = idx & 127;
            float w = exp2f((float)(CC - 1 - (j0 + j)) * LG2G);
            Ks[j][h] = Kp[(size_t)(j0 + j) * HH + h] * w;
            Vs[j][h] = Vp[(size_t)(j0 + j) * HH + h];
        }
        __syncthreads();
        #pragma unroll
        for (int j = 0; j < 16; j++) {
            float4 k0 = *(const float4*)&Ks[j][h1b];
            float4 k1 = *(const float4*)&Ks[j][h1b + 4];
            float4 v0 = *(const float4*)&Vs[j][h2b];
            float4 v1 = *(const float4*)&Vs[j][h2b + 4];
            float kr[8] = {k0.x, k0.y, k0.z, k0.w, k1.x, k1.y, k1.z, k1.w};
            float vr[8] = {v0.x, v0.y, v0.z, v0.w, v1.x, v1.y, v1.z, v1.w};
            #pragma unroll
            for (int r = 0; r < 8; r++)
                #pragma unroll
                for (int cc2 = 0; cc2 < 8; cc2++)
                    acc[r][cc2] = fmaf(kr[r], vr[cc2], acc[r][cc2]);
        }
        __syncthreads();
    }
    #pragma unroll
    for (int r = 0; r < 8; r++)
        #pragma unroll
        for (int cc2 = 0; cc2 < 8; cc2++)
            Ap[(size_t)(h1b + r) * HH + h2b + cc2] = acc[r][cc2];
}

// ====================================================================
// Kernel 3: prefix scan over chunks
//   St_0 = 0;  St_{c+1} = gamma^C * St_c + A_c
// ====================================================================
__global__ void scan_kernel()
{
    int e = blockIdx.x * 256 + threadIdx.x;     // 0 .. B*H*H-1
    int b = e >> 14;
    int off = e & 16383;
    float st = 0.f;
    const float dC = exp2f((float)CC * LG2G);   // gamma^128
    for (int c = 0; c < NCHUNK; c++) {
        size_t idx = (((size_t)(b * NCHUNK + c)) << 14) + off;
        g_St[idx] = st;
        st = st * dC + g_A[idx];
    }
}

// ====================================================================
// Kernel 4: per-(b,chunk) output.
//   Sc[i,j] = (Q_i . K_j) * gamma^(i-j) for j<=i else 0
//   O[i]    = Sc @ V_chunk + (gamma^(i+1) Q_i) @ State_c
// dyn smem = 128*132*4 + 2*16*132*4 = 84480 B
// ====================================================================
#define SC_LD 132
#define K4_SMEM (128*SC_LD*4 + 2*16*SC_LD*4)

__global__ void out_kernel(float* __restrict__ out)
{
    extern __shared__ float smem[];
    float* Sc = smem;                                   // [128][132]
    float (*bufA)[SC_LD] = (float(*)[SC_LD])(smem + 128 * SC_LD);
    float (*bufB)[SC_LD] = (float(*)[SC_LD])(smem + 128 * SC_LD + 16 * SC_LD);

    int bc = blockIdx.x;
    int b = bc >> 5;
    int c = bc & 31;
    const float* Qp = g_Q + (size_t)(b * SS + c * CC) * HH;
    const float* Kp = g_K + (size_t)(b * SS + c * CC) * HH;
    const float* Vp = g_V + (size_t)(b * SS + c * CC) * HH;
    const float* Sp = g_St + (size_t)bc * HH * HH;

    const int tid = threadIdx.x;
    const int tx = tid & 15, ty = tid >> 4;
    const int ib = ty * 8;      // row block (i)
    const int jb = tx * 8;      // col block (j or h2)

    float acc[8][8];
    #pragma unroll
    for (int r = 0; r < 8; r++)
        #pragma unroll
        for (int cc2 = 0; cc2 < 8; cc2++) acc[r][cc2] = 0.f;

    // ---- Phase 1: scores = Q K^T ----
    for (int h0 = 0; h0 < HH; h0 += 16) {
        #pragma unroll
        for (int i = 0; i < 8; i++) {
            int idx = i * 256 + tid;
            int row = idx >> 4;     // 0..127
            int hh  = idx & 15;
            bufA[hh][row] = Qp[(size_t)row * HH + h0 + hh];
            bufB[hh][row] = Kp[(size_t)row * HH + h0 + hh];
        }
        __syncthreads();
        #pragma unroll
        for (int hh = 0; hh < 16; hh++) {
            float4 q0 = *(const float4*)&bufA[hh][ib];
            float4 q1 = *(const float4*)&bufA[hh][ib + 4];
            float4 k0 = *(const float4*)&bufB[hh][jb];
            float4 k1 = *(const float4*)&bufB[hh][jb + 4];
            float qr[8] = {q0.x, q0.y, q0.z, q0.w, q1.x, q1.y, q1.z, q1.w};
            float kr[8] = {k0.x, k0.y, k0.z, k0.w, k1.x, k1.y, k1.z, k1.w};
            #pragma unroll
            for (int r = 0; r < 8; r++)
                #pragma unroll
                for (int cc2 = 0; cc2 < 8; cc2++)
                    acc[r][cc2] = fmaf(qr[r], kr[cc2], acc[r][cc2]);
        }
        __syncthreads();
    }

    // ---- Phase 2: apply causal decay mask, store to smem ----
    #pragma unroll
    for (int r = 0; r < 8; r++) {
        int i = ib + r;
        #pragma unroll
        for (int cc2 = 0; cc2 < 8; cc2++) {
            int j = jb + cc2;
            float val = (j <= i) ? acc[r][cc2] * exp2f((float)(i - j) * LG2G) : 0.f;
            Sc[i * SC_LD + j] = val;
            acc[r][cc2] = 0.f;   // reuse as output accumulator
        }
    }
    __syncthreads();

    // ---- Phase 3a: O += Sc @ V ----
    for (int j0 = 0; j0 < CC; j0 += 16) {
        #pragma unroll
        for (int i = 0; i < 8; i++) {       // FIXED: 16 rows x 128 cols = 8 iters
            int idx = i * 256 + tid;
            int j = idx >> 7;
            int h = idx & 127;
            bufA[j][h] = Vp[(size_t)(j0 + j) * HH + h];
        }
        __syncthreads();
        #pragma unroll
        for (int j = 0; j < 16; j++) {
            float vr[8];
            float4 v0 = *(const float4*)&bufA[j][jb];
            float4 v1 = *(const float4*)&bufA[j][jb + 4];
            vr[0]=v0.x; vr[1]=v0.y; vr[2]=v0.z; vr[3]=v0.w;
            vr[4]=v1.x; vr[5]=v1.y; vr[6]=v1.z; vr[7]=v1.w;
            #pragma unroll
            for (int r = 0; r < 8; r++) {
                float s = Sc[(ib + r) * SC_LD + j0 + j];
                #pragma unroll
                for (int cc2 = 0; cc2 < 8; cc2++)
                    acc[r][cc2] = fmaf(s, vr[cc2], acc[r][cc2]);
            }
        }
        __syncthreads();
    }

    // ---- Phase 3b: O += (gamma^(i+1) Q) @ State ----
    for (int h0 = 0; h0 < HH; h0 += 16) {
        #pragma unroll
        for (int i = 0; i < 8; i++) {
            int idx = i * 256 + tid;
            int row = idx >> 4;
            int hh  = idx & 15;
            float w = exp2f((float)(row + 1) * LG2G);   // gamma^(i+1)
            bufA[hh][row] = Qp[(size_t)row * HH + h0 + hh] * w;
        }
        #pragma unroll
        for (int i = 0; i < 8; i++) {       // FIXED: 16 rows x 128 cols = 8 iters
            int idx = i * 256 + tid;
            int hh = idx >> 7;
            int h2 = idx & 127;
            bufB[hh][h2] = Sp[(size_t)(h0 + hh) * HH + h2];
        }
        __syncthreads();
        #pragma unroll
        for (int hh = 0; hh < 16; hh++) {
            float4 q0 = *(const float4*)&bufA[hh][ib];
            float4 q1 = *(const float4*)&bufA[hh][ib + 4];
            float4 s0 = *(const float4*)&bufB[hh][jb];
            float4 s1 = *(const float4*)&bufB[hh][jb + 4];
            float qr[8] = {q0.x, q0.y, q0.z, q0.w, q1.x, q1.y, q1.z, q1.w};
            float sr[8] = {s0.x, s0.y, s0.z, s0.w, s1.x, s1.y, s1.z, s1.w};
            #pragma unroll
            for (int r = 0; r < 8; r++)
                #pragma unroll
                for (int cc2 = 0; cc2 < 8; cc2++)
                    acc[r][cc2] = fmaf(qr[r], sr[cc2], acc[r][cc2]);
        }
        __syncthreads();
    }

    // ---- store ----
    #pragma unroll
    for (int r = 0; r < 8; r++) {
        float* orow = out + (size_t)(b * SS + c * CC + ib + r) * HH;
        #pragma unroll
        for (int cc2 = 0; cc2 < 8; cc2++)
            orow[jb + cc2] = acc[r][cc2];
    }
}

// ====================================================================
extern "C" void kernel_launch(void* const* d_in, const int* in_sizes, int n_in,
                              void* d_out, int out_size)
{
    const float* q  = (const float*)d_in[0];
    const float* k  = (const float*)d_in[1];
    const float* v  = (const float*)d_in[2];
    const float* Wq = (const float*)d_in[3];
    const float* bq = (const float*)d_in[4];
    const float* Wk = (const float*)d_in[5];
    const float* bk = (const float*)d_in[6];
    const float* Wv = (const float*)d_in[7];
    const float* bv = (const float*)d_in[8];
    float* out = (float*)d_out;

    // projections + xpos
    dim3 g1((BB * SS) / BM, 1, 3);
    proj_xpos_kernel<<<g1, 256>>>(q, k, v, Wq, bq, Wk, bk, Wv, bv);

    // per-chunk KV summaries
    chunk_kv_kernel<<<BB * NCHUNK, 256>>>();

    // prefix-scan states
    scan_kernel<<<(BB * HH * HH) / 256, 256>>>();

    // outputs
    cudaFuncSetAttribute(out_kernel, cudaFuncAttributeMaxDynamicSharedMemorySize, K4_SMEM);
    out_kernel<<<BB * NCHUNK, 256, K4_SMEM>>>(out);
}

// round 4
// speedup vs baseline: 2.3641x; 2.3641x over previous
#include <cuda_runtime.h>
#include <cuda_bf16.h>
#include <math.h>
#include <stdint.h>

// Problem constants
#define BB 4
#define SS 4096
#define EE 1024
#define HH 128
#define CC 128
#define NCHUNK (SS/CC)
#define LG2G  (-0.04580368938794f)
#define LOG2_10000 13.287712379549449

// -------- scratch --------
__device__ float g_Q[BB*SS*HH];
__device__ float g_K[BB*SS*HH];
__device__ float g_V[BB*SS*HH];
__device__ float g_A[BB*NCHUNK*HH*HH];
__device__ float g_St[BB*NCHUNK*HH*HH];
// xpos tables: [d][s1] / [d][s0]; (sin, cos, scale, 1/scale)
__device__ float4 g_tabA[64][64];
__device__ float4 g_tabB[64][64];

// ==================== table build ====================
__global__ void build_tab_kernel() {
    int idx = blockIdx.x * 256 + threadIdx.x;      // 0..8191
    int which = idx >> 12;
    int d  = (idx >> 6) & 63;
    int sX = idx & 63;
    double invf = exp2(-(double)d * (LOG2_10000 / 64.0));
    float sv = (2.0f * (float)d + 51.2f) * (1.0f / 179.2f);
    float ang, pw;
    if (which == 0) { ang = (float)((double)(sX * 64) * invf); pw = powf(sv, (float)sX * 0.125f); }
    else            { ang = (float)((double)sX * invf);        pw = powf(sv, (float)sX * (1.0f/512.0f)); }
    float sn, cs; sincosf(ang, &sn, &cs);
    float4 r = make_float4(sn, cs, pw, 1.0f / pw);
    if (which == 0) g_tabA[d][sX] = r; else g_tabB[d][sX] = r;
}

// ==================== mma.sync helpers (sm_80+ PTX, arch-neutral) ====================
__device__ __forceinline__ void mma_bf16(float* d, const uint32_t* a, uint32_t b0, uint32_t b1) {
    asm volatile("mma.sync.aligned.m16n8k16.row.col.f32.bf16.bf16.f32 "
        "{%0,%1,%2,%3}, {%4,%5,%6,%7}, {%8,%9}, {%0,%1,%2,%3};"
        : "+f"(d[0]), "+f"(d[1]), "+f"(d[2]), "+f"(d[3])
        : "r"(a[0]), "r"(a[1]), "r"(a[2]), "r"(a[3]), "r"(b0), "r"(b1));
}

// split fp32x4 into bf16 hi/lo, store as uint2 at byte offset
__device__ __forceinline__ void split_store(char* hiP, char* loP, uint32_t off, float4 v) {
    uint32_t hi01, hi23;
    asm("cvt.rn.bf16x2.f32 %0, %1, %2;" : "=r"(hi01) : "f"(v.y), "f"(v.x));
    asm("cvt.rn.bf16x2.f32 %0, %1, %2;" : "=r"(hi23) : "f"(v.w), "f"(v.z));
    float l0 = v.x - __uint_as_float(hi01 << 16);
    float l1 = v.y - __uint_as_float(hi01 & 0xFFFF0000u);
    float l2 = v.z - __uint_as_float(hi23 << 16);
    float l3 = v.w - __uint_as_float(hi23 & 0xFFFF0000u);
    uint32_t lo01, lo23;
    asm("cvt.rn.bf16x2.f32 %0, %1, %2;" : "=r"(lo01) : "f"(l1), "f"(l0));
    asm("cvt.rn.bf16x2.f32 %0, %1, %2;" : "=r"(lo23) : "f"(l3), "f"(l2));
    *(uint2*)(hiP + off) = make_uint2(hi01, hi23);
    *(uint2*)(loP + off) = make_uint2(lo01, lo23);
}

// ==================== projection GEMM: bf16x3 emulated fp32 via mma.sync ====================
// C[128m x 128n] per block; K=1024 in chunks of 32; smem tiles 128 x 32 bf16, row stride 72B.
#define ROWB 72
#define TILEB (128*ROWB)          // 9216 B per tile
#define PROJ_SMEM (8*TILEB)       // 2 stages * 4 tiles = 73728 B

__device__ __forceinline__ uint32_t lds32(const char* base, int row, int word) {
    return *(const uint32_t*)(base + row * ROWB + word * 4);
}

__global__ __launch_bounds__(256, 1)
void proj_mma_kernel(const float* __restrict__ q, const float* __restrict__ k,
                     const float* __restrict__ v,
                     const float* __restrict__ Wq, const float* __restrict__ bq,
                     const float* __restrict__ Wk, const float* __restrict__ bk,
                     const float* __restrict__ Wv, const float* __restrict__ bv)
{
    extern __shared__ char sm[];
    __shared__ float s_bias[HH];

    const int z = blockIdx.y;
    const float* X   = (z == 0) ? q  : (z == 1) ? k  : v;
    const float* W   = (z == 0) ? Wq : (z == 1) ? Wk : Wv;
    const float* bia = (z == 0) ? bq : (z == 1) ? bk : bv;
    float* OUT       = (z == 0) ? g_Q : (z == 1) ? g_K : g_V;

    const int tid  = threadIdx.x;
    const int wid  = tid >> 5;
    const int lane = tid & 31;
    const int warpM = wid & 3;          // 4 warps over M (32 rows each)
    const int warpN = wid >> 2;         // 2 warps over N (64 cols each)
    const int m0 = blockIdx.x * 128;

    if (tid < HH) s_bias[tid] = bia[tid];

    // tile(stage, which): which 0=Ahi 1=Alo 2=Whi 3=Wlo
    #define TILE_PTR(s, wch) (sm + ((s) * 4 + (wch)) * TILEB)

    float acc[2][8][4];
    #pragma unroll
    for (int r = 0; r < 2; r++)
        #pragma unroll
        for (int j = 0; j < 8; j++)
            #pragma unroll
            for (int c = 0; c < 4; c++) acc[r][j][c] = 0.f;

    // per-thread gmem tile coords: 128 rows x 8 float4 (32 cols)
    const int ldRow = tid >> 3;         // base row (stride 32 over 4 iters)
    const int ldC4  = tid & 7;
    float4 aV[4], wV[4];

    // prefetch chunk 0
    #pragma unroll
    for (int it = 0; it < 4; it++) {
        int row = ldRow + it * 32;
        aV[it] = *(const float4*)&X[(size_t)(m0 + row) * EE + ldC4 * 4];
        wV[it] = *(const float4*)&W[(size_t)row * EE + ldC4 * 4];
    }
    {
        uint32_t off = (uint32_t)ldRow * ROWB + ldC4 * 8;
        #pragma unroll
        for (int it = 0; it < 4; it++) {
            split_store(TILE_PTR(0,0), TILE_PTR(0,1), off + it * 32 * ROWB, aV[it]);
            split_store(TILE_PTR(0,2), TILE_PTR(0,3), off + it * 32 * ROWB, wV[it]);
        }
    }
    __syncthreads();

    const int rA = lane >> 2;           // 0..7
    const int wBase = lane & 3;         // word within k16 window

    for (int i = 0; i < 32; i++) {
        const int s = i & 1;
        if (i < 31) {
            const int k0 = (i + 1) * 32;
            #pragma unroll
            for (int it = 0; it < 4; it++) {
                int row = ldRow + it * 32;
                aV[it] = *(const float4*)&X[(size_t)(m0 + row) * EE + k0 + ldC4 * 4];
                wV[it] = *(const float4*)&W[(size_t)row * EE + k0 + ldC4 * 4];
            }
        }

        const char* Ah = TILE_PTR(s, 0);
        const char* Al = TILE_PTR(s, 1);
        const char* Wh = TILE_PTR(s, 2);
        const char* Wl = TILE_PTR(s, 3);

        #pragma unroll
        for (int k16 = 0; k16 < 2; k16++) {
            const int w = k16 * 8 + wBase;
            uint32_t ahi[2][4], alo[2][4];
            #pragma unroll
            for (int r = 0; r < 2; r++) {
                int row = warpM * 32 + r * 16 + rA;
                ahi[r][0] = lds32(Ah, row,     w);
                ahi[r][1] = lds32(Ah, row + 8, w);
                ahi[r][2] = lds32(Ah, row,     w + 4);
                ahi[r][3] = lds32(Ah, row + 8, w + 4);
                alo[r][0] = lds32(Al, row,     w);
                alo[r][1] = lds32(Al, row + 8, w);
                alo[r][2] = lds32(Al, row,     w + 4);
                alo[r][3] = lds32(Al, row + 8, w + 4);
            }
            #pragma unroll
            for (int j = 0; j < 8; j++) {
                int n = warpN * 64 + j * 8 + rA;
                uint32_t bh0 = lds32(Wh, n, w);
                uint32_t bh1 = lds32(Wh, n, w + 4);
                uint32_t bl0 = lds32(Wl, n, w);
                uint32_t bl1 = lds32(Wl, n, w + 4);
                #pragma unroll
                for (int r = 0; r < 2; r++) {
                    mma_bf16(acc[r][j], ahi[r], bh0, bh1);
                    mma_bf16(acc[r][j], ahi[r], bl0, bl1);
                    mma_bf16(acc[r][j], alo[r], bh0, bh1);
                }
            }
        }

        if (i < 31) {
            uint32_t off = (uint32_t)ldRow * ROWB + ldC4 * 8;
            const int ns = (i + 1) & 1;
            #pragma unroll
            for (int it = 0; it < 4; it++) {
                split_store(TILE_PTR(ns,0), TILE_PTR(ns,1), off + it * 32 * ROWB, aV[it]);
                split_store(TILE_PTR(ns,2), TILE_PTR(ns,3), off + it * 32 * ROWB, wV[it]);
            }
            __syncthreads();
        }
    }

    // ---- epilogue: bias + xpos, write fp32 ----
    #pragma unroll
    for (int r = 0; r < 2; r++) {
        #pragma unroll
        for (int half = 0; half < 2; half++) {
            const int m = m0 + warpM * 32 + r * 16 + rA + half * 8;
            const int sIdx = m & (SS - 1);
            const int s1 = sIdx >> 6;
            const int s0 = sIdx & 63;
            float* orow = OUT + (size_t)m * HH;
            #pragma unroll
            for (int j = 0; j < 8; j++) {
                const int h = warpN * 64 + j * 8 + wBase * 2;
                float x0 = acc[r][j][half * 2 + 0] + s_bias[h];
                float x1 = acc[r][j][half * 2 + 1] + s_bias[h + 1];
                if (z == 2) {
                    *(float2*)&orow[h] = make_float2(x0, x1);
                } else {
                    const int d = h >> 1;
                    float4 A4 = g_tabA[d][s1];
                    float4 B4 = g_tabB[d][s0];
                    float sn = A4.x * B4.y + A4.y * B4.x;
                    float cs = A4.y * B4.y - A4.x * B4.x;
                    float sc = (z == 0) ? A4.z * B4.z : A4.w * B4.w;
                    sn *= sc; cs *= sc;
                    *(float2*)&orow[h] = make_float2(x0 * cs - x1 * sn, x1 * cs + x0 * sn);
                }
            }
        }
    }
    #undef TILE_PTR
}

// ==================== chunk KV summaries ====================
__global__ void chunk_kv_kernel()
{
    int bc = blockIdx.x;
    int b = bc >> 5;
    int c = bc & 31;
    const float* Kp = g_K + (size_t)(b * SS + c * CC) * HH;
    const float* Vp = g_V + (size_t)(b * SS + c * CC) * HH;
    float* Ap = g_A + (size_t)bc * HH * HH;

    __shared__ float Ks[16][HH + 4];
    __shared__ float Vs[16][HH + 4];

    const int tid = threadIdx.x;
    const int tx = tid & 15, ty = tid >> 4;
    const int h1b = ty * 8, h2b = tx * 8;

    float acc[8][8];
    #pragma unroll
    for (int r = 0; r < 8; r++)
        #pragma unroll
        for (int cc2 = 0; cc2 < 8; cc2++) acc[r][cc2] = 0.f;

    for (int j0 = 0; j0 < CC; j0 += 16) {
        #pragma unroll
        for (int i = 0; i < 8; i++) {
            int idx = i * 256 + tid;
            int j = idx >> 7;
            int h = idx & 127;
            float w = exp2f((float)(CC - 1 - (j0 + j)) * LG2G);
            Ks[j][h] = Kp[(size_t)(j0 + j) * HH + h] * w;
            Vs[j][h] = Vp[(size_t)(j0 + j) * HH + h];
        }
        __syncthreads();
        #pragma unroll
        for (int j = 0; j < 16; j++) {
            float4 k0 = *(const float4*)&Ks[j][h1b];
            float4 k1 = *(const float4*)&Ks[j][h1b + 4];
            float4 v0 = *(const float4*)&Vs[j][h2b];
            float4 v1 = *(const float4*)&Vs[j][h2b + 4];
            float kr[8] = {k0.x, k0.y, k0.z, k0.w, k1.x, k1.y, k1.z, k1.w};
            float vr[8] = {v0.x, v0.y, v0.z, v0.w, v1.x, v1.y, v1.z, v1.w};
            #pragma unroll
            for (int r = 0; r < 8; r++)
                #pragma unroll
                for (int cc2 = 0; cc2 < 8; cc2++)
                    acc[r][cc2] = fmaf(kr[r], vr[cc2], acc[r][cc2]);
        }
        __syncthreads();
    }
    #pragma unroll
    for (int r = 0; r < 8; r++)
        #pragma unroll
        for (int cc2 = 0; cc2 < 8; cc2++)
            Ap[(size_t)(h1b + r) * HH + h2b + cc2] = acc[r][cc2];
}

// ==================== prefix scan ====================
__global__ void scan_kernel()
{
    int e = blockIdx.x * 256 + threadIdx.x;
    int b = e >> 14;
    int off = e & 16383;
    float st = 0.f;
    const float dC = exp2f((float)CC * LG2G);
    for (int c = 0; c < NCHUNK; c++) {
        size_t idx = (((size_t)(b * NCHUNK + c)) << 14) + off;
        g_St[idx] = st;
        st = st * dC + g_A[idx];
    }
}

// ==================== per-chunk output ====================
#define SC_LD 132
#define K4_SMEM (128*SC_LD*4 + 2*16*SC_LD*4)

__global__ void out_kernel(float* __restrict__ out)
{
    extern __shared__ float smem[];
    float* Sc = smem;
    float (*bufA)[SC_LD] = (float(*)[SC_LD])(smem + 128 * SC_LD);
    float (*bufB)[SC_LD] = (float(*)[SC_LD])(smem + 128 * SC_LD + 16 * SC_LD);

    int bc = blockIdx.x;
    int b = bc >> 5;
    int c = bc & 31;
    const float* Qp = g_Q + (size_t)(b * SS + c * CC) * HH;
    const float* Kp = g_K + (size_t)(b * SS + c * CC) * HH;
    const float* Vp = g_V + (size_t)(b * SS + c * CC) * HH;
    const float* Sp = g_St + (size_t)bc * HH * HH;

    const int tid = threadIdx.x;
    const int tx = tid & 15, ty = tid >> 4;
    const int ib = ty * 8;
    const int jb = tx * 8;

    float acc[8][8];
    #pragma unroll
    for (int r = 0; r < 8; r++)
        #pragma unroll
        for (int cc2 = 0; cc2 < 8; cc2++) acc[r][cc2] = 0.f;

    for (int h0 = 0; h0 < HH; h0 += 16) {
        #pragma unroll
        for (int i = 0; i < 8; i++) {
            int idx = i * 256 + tid;
            int row = idx >> 4;
            int hh  = idx & 15;
            bufA[hh][row] = Qp[(size_t)row * HH + h0 + hh];
            bufB[hh][row] = Kp[(size_t)row * HH + h0 + hh];
        }
        __syncthreads();
        #pragma unroll
        for (int hh = 0; hh < 16; hh++) {
            float4 q0 = *(const float4*)&bufA[hh][ib];
            float4 q1 = *(const float4*)&bufA[hh][ib + 4];
            float4 k0 = *(const float4*)&bufB[hh][jb];
            float4 k1 = *(const float4*)&bufB[hh][jb + 4];
            float qr[8] = {q0.x, q0.y, q0.z, q0.w, q1.x, q1.y, q1.z, q1.w};
            float kr[8] = {k0.x, k0.y, k0.z, k0.w, k1.x, k1.y, k1.z, k1.w};
            #pragma unroll
            for (int r = 0; r < 8; r++)
                #pragma unroll
                for (int cc2 = 0; cc2 < 8; cc2++)
                    acc[r][cc2] = fmaf(qr[r], kr[cc2], acc[r][cc2]);
        }
        __syncthreads();
    }

    #pragma unroll
    for (int r = 0; r < 8; r++) {
        int i = ib + r;
        #pragma unroll
        for (int cc2 = 0; cc2 < 8; cc2++) {
            int j = jb + cc2;
            float val = (j <= i) ? acc[r][cc2] * exp2f((float)(i - j) * LG2G) : 0.f;
            Sc[i * SC_LD + j] = val;
            acc[r][cc2] = 0.f;
        }
    }
    __syncthreads();

    for (int j0 = 0; j0 < CC; j0 += 16) {
        #pragma unroll
        for (int i = 0; i < 8; i++) {
            int idx = i * 256 + tid;
            int j = idx >> 7;
            int h = idx & 127;
            bufA[j][h] = Vp[(size_t)(j0 + j) * HH + h];
        }
        __syncthreads();
        #pragma unroll
        for (int j = 0; j < 16; j++) {
            float vr[8];
            float4 v0 = *(const float4*)&bufA[j][jb];
            float4 v1 = *(const float4*)&bufA[j][jb + 4];
            vr[0]=v0.x; vr[1]=v0.y; vr[2]=v0.z; vr[3]=v0.w;
            vr[4]=v1.x; vr[5]=v1.y; vr[6]=v1.z; vr[7]=v1.w;
            #pragma unroll
            for (int r = 0; r < 8; r++) {
                float s = Sc[(ib + r) * SC_LD + j0 + j];
                #pragma unroll
                for (int cc2 = 0; cc2 < 8; cc2++)
                    acc[r][cc2] = fmaf(s, vr[cc2], acc[r][cc2]);
            }
        }
        __syncthreads();
    }

    for (int h0 = 0; h0 < HH; h0 += 16) {
        #pragma unroll
        for (int i = 0; i < 8; i++) {
            int idx = i * 256 + tid;
            int row = idx >> 4;
            int hh  = idx & 15;
            float w = exp2f((float)(row + 1) * LG2G);
            bufA[hh][row] = Qp[(size_t)row * HH + h0 + hh] * w;
        }
        #pragma unroll
        for (int i = 0; i < 8; i++) {
            int idx = i * 256 + tid;
            int hh = idx >> 7;
            int h2 = idx & 127;
            bufB[hh][h2] = Sp[(size_t)(h0 + hh) * HH + h2];
        }
        __syncthreads();
        #pragma unroll
        for (int hh = 0; hh < 16; hh++) {
            float4 q0 = *(const float4*)&bufA[hh][ib];
            float4 q1 = *(const float4*)&bufA[hh][ib + 4];
            float4 s0 = *(const float4*)&bufB[hh][jb];
            float4 s1 = *(const float4*)&bufB[hh][jb + 4];
            float qr[8] = {q0.x, q0.y, q0.z, q0.w, q1.x, q1.y, q1.z, q1.w};
            float sr[8] = {s0.x, s0.y, s0.z, s0.w, s1.x, s1.y, s1.z, s1.w};
            #pragma unroll
            for (int r = 0; r < 8; r++)
                #pragma unroll
                for (int cc2 = 0; cc2 < 8; cc2++)
                    acc[r][cc2] = fmaf(qr[r], sr[cc2], acc[r][cc2]);
        }
        __syncthreads();
    }

    #pragma unroll
    for (int r = 0; r < 8; r++) {
        float* orow = out + (size_t)(b * SS + c * CC + ib + r) * HH;
        #pragma unroll
        for (int cc2 = 0; cc2 < 8; cc2++)
            orow[jb + cc2] = acc[r][cc2];
    }
}

// ====================================================================
extern "C" void kernel_launch(void* const* d_in, const int* in_sizes, int n_in,
                              void* d_out, int out_size)
{
    const float* q  = (const float*)d_in[0];
    const float* k  = (const float*)d_in[1];
    const float* v  = (const float*)d_in[2];
    const float* Wq = (const float*)d_in[3];
    const float* bq = (const float*)d_in[4];
    const float* Wk = (const float*)d_in[5];
    const float* bk = (const float*)d_in[6];
    const float* Wv = (const float*)d_in[7];
    const float* bv = (const float*)d_in[8];
    float* out = (float*)d_out;

    cudaFuncSetAttribute(proj_mma_kernel, cudaFuncAttributeMaxDynamicSharedMemorySize, PROJ_SMEM);
    cudaFuncSetAttribute(out_kernel, cudaFuncAttributeMaxDynamicSharedMemorySize, K4_SMEM);

    build_tab_kernel<<<32, 256>>>();

    dim3 gproj(128, 3, 1);
    proj_mma_kernel<<<gproj, 256, PROJ_SMEM>>>(q, k, v, Wq, bq, Wk, bk, Wv, bv);

    chunk_kv_kernel<<<BB * NCHUNK, 256>>>();
    scan_kernel<<<(BB * HH * HH) / 256, 256>>>();
    out_kernel<<<BB * NCHUNK, 256, K4_SMEM>>>(out);
}

// round 6
// speedup vs baseline: 2.7475x; 1.1622x over previous
#include <cuda_runtime.h>
#include <cuda_bf16.h>
#include <math.h>
#include <stdint.h>

// Problem constants
#define BB 4
#define SS 4096
#define EE 1024
#define HH 128
#define CC 128
#define NCHUNK (SS/CC)
#define GAMMA 0.96875f
#define LG2G  (-0.04580368938794f)
#define LOG2_10000 13.287712379549449

// -------- scratch --------
__device__ float g_Q[BB*SS*HH];
__device__ float g_K[BB*SS*HH];
__device__ float g_V[BB*SS*HH];
__device__ float g_A[BB*NCHUNK*HH*HH];                 // T_c = A_c^T  [h2][h1], fp32
__device__ __nv_bfloat16 g_Sth[BB*NCHUNK*HH*HH];       // state hi, [h2][h1]
__device__ __nv_bfloat16 g_Stl[BB*NCHUNK*HH*HH];       // state lo
// xpos tables: [d][s1] / [d][s0]; (sin, cos, scale, 1/scale)
__device__ float4 g_tabA[64][64];
__device__ float4 g_tabB[64][64];

// ==================== table build ====================
__global__ void build_tab_kernel() {
    int idx = blockIdx.x * 256 + threadIdx.x;      // 0..8191
    int which = idx >> 12;
    int d  = (idx >> 6) & 63;
    int sX = idx & 63;
    double invf = exp2(-(double)d * (LOG2_10000 / 64.0));
    float sv = (2.0f * (float)d + 51.2f) * (1.0f / 179.2f);
    float ang, pw;
    if (which == 0) { ang = (float)((double)(sX * 64) * invf); pw = powf(sv, (float)sX * 0.125f); }
    else            { ang = (float)((double)sX * invf);        pw = powf(sv, (float)sX * (1.0f/512.0f)); }
    float sn, cs; sincosf(ang, &sn, &cs);
    float4 r = make_float4(sn, cs, pw, 1.0f / pw);
    if (which == 0) g_tabA[d][sX] = r; else g_tabB[d][sX] = r;
}

// ==================== mma.sync helpers ====================
__device__ __forceinline__ void mma_bf16(float* d, const uint32_t* a, uint32_t b0, uint32_t b1) {
    asm volatile("mma.sync.aligned.m16n8k16.row.col.f32.bf16.bf16.f32 "
        "{%0,%1,%2,%3}, {%4,%5,%6,%7}, {%8,%9}, {%0,%1,%2,%3};"
        : "+f"(d[0]), "+f"(d[1]), "+f"(d[2]), "+f"(d[3])
        : "r"(a[0]), "r"(a[1]), "r"(a[2]), "r"(a[3]), "r"(b0), "r"(b1));
}

// pack two fp32 into bf16x2 (x in low half, y in high half)
__device__ __forceinline__ uint32_t pack_bf16x2(float x, float y) {
    uint32_t r;
    asm("cvt.rn.bf16x2.f32 %0, %1, %2;" : "=r"(r) : "f"(y), "f"(x));
    return r;
}

// split fp32x4 into bf16 hi/lo, store as uint2 at byte offset
__device__ __forceinline__ void split_store(char* hiP, char* loP, uint32_t off, float4 v) {
    uint32_t hi01 = pack_bf16x2(v.x, v.y);
    uint32_t hi23 = pack_bf16x2(v.z, v.w);
    float l0 = v.x - __uint_as_float(hi01 << 16);
    float l1 = v.y - __uint_as_float(hi01 & 0xFFFF0000u);
    float l2 = v.z - __uint_as_float(hi23 << 16);
    float l3 = v.w - __uint_as_float(hi23 & 0xFFFF0000u);
    uint32_t lo01 = pack_bf16x2(l0, l1);
    uint32_t lo23 = pack_bf16x2(l2, l3);
    *(uint2*)(hiP + off) = make_uint2(hi01, hi23);
    *(uint2*)(loP + off) = make_uint2(lo01, lo23);
}

// split single fp32 -> (hi bf16, lo bf16)
__device__ __forceinline__ void split1(float x, __nv_bfloat16& h, __nv_bfloat16& l) {
    h = __float2bfloat16(x);
    l = __float2bfloat16(x - __bfloat162float(h));
}

// ==================== projection GEMM (unchanged from R4) ====================
#define ROWB 72
#define TILEB (128*ROWB)
#define PROJ_SMEM (8*TILEB)

__device__ __forceinline__ uint32_t lds32(const char* base, int row, int word) {
    return *(const uint32_t*)(base + row * ROWB + word * 4);
}

__global__ __launch_bounds__(256, 1)
void proj_mma_kernel(const float* __restrict__ q, const float* __restrict__ k,
                     const float* __restrict__ v,
                     const float* __restrict__ Wq, const float* __restrict__ bq,
                     const float* __restrict__ Wk, const float* __restrict__ bk,
                     const float* __restrict__ Wv, const float* __restrict__ bv)
{
    extern __shared__ char sm[];
    __shared__ float s_bias[HH];

    const int z = blockIdx.y;
    const float* X   = (z == 0) ? q  : (z == 1) ? k  : v;
    const float* W   = (z == 0) ? Wq : (z == 1) ? Wk : Wv;
    const float* bia = (z == 0) ? bq : (z == 1) ? bk : bv;
    float* OUT       = (z == 0) ? g_Q : (z == 1) ? g_K : g_V;

    const int tid  = threadIdx.x;
    const int wid  = tid >> 5;
    const int lane = tid & 31;
    const int warpM = wid & 3;
    const int warpN = wid >> 2;
    const int m0 = blockIdx.x * 128;

    if (tid < HH) s_bias[tid] = bia[tid];

    #define TILE_PTR(s, wch) (sm + ((s) * 4 + (wch)) * TILEB)

    float acc[2][8][4];
    #pragma unroll
    for (int r = 0; r < 2; r++)
        #pragma unroll
        for (int j = 0; j < 8; j++)
            #pragma unroll
            for (int c = 0; c < 4; c++) acc[r][j][c] = 0.f;

    const int ldRow = tid >> 3;
    const int ldC4  = tid & 7;
    float4 aV[4], wV[4];

    #pragma unroll
    for (int it = 0; it < 4; it++) {
        int row = ldRow + it * 32;
        aV[it] = *(const float4*)&X[(size_t)(m0 + row) * EE + ldC4 * 4];
        wV[it] = *(const float4*)&W[(size_t)row * EE + ldC4 * 4];
    }
    {
        uint32_t off = (uint32_t)ldRow * ROWB + ldC4 * 8;
        #pragma unroll
        for (int it = 0; it < 4; it++) {
            split_store(TILE_PTR(0,0), TILE_PTR(0,1), off + it * 32 * ROWB, aV[it]);
            split_store(TILE_PTR(0,2), TILE_PTR(0,3), off + it * 32 * ROWB, wV[it]);
        }
    }
    __syncthreads();

    const int rA = lane >> 2;
    const int wBase = lane & 3;

    for (int i = 0; i < 32; i++) {
        const int s = i & 1;
        if (i < 31) {
            const int k0 = (i + 1) * 32;
            #pragma unroll
            for (int it = 0; it < 4; it++) {
                int row = ldRow + it * 32;
                aV[it] = *(const float4*)&X[(size_t)(m0 + row) * EE + k0 + ldC4 * 4];
                wV[it] = *(const float4*)&W[(size_t)row * EE + k0 + ldC4 * 4];
            }
        }

        const char* Ah = TILE_PTR(s, 0);
        const char* Al = TILE_PTR(s, 1);
        const char* Wh = TILE_PTR(s, 2);
        const char* Wl = TILE_PTR(s, 3);

        #pragma unroll
        for (int k16 = 0; k16 < 2; k16++) {
            const int w = k16 * 8 + wBase;
            uint32_t ahi[2][4], alo[2][4];
            #pragma unroll
            for (int r = 0; r < 2; r++) {
                int row = warpM * 32 + r * 16 + rA;
                ahi[r][0] = lds32(Ah, row,     w);
                ahi[r][1] = lds32(Ah, row + 8, w);
                ahi[r][2] = lds32(Ah, row,     w + 4);
                ahi[r][3] = lds32(Ah, row + 8, w + 4);
                alo[r][0] = lds32(Al, row,     w);
                alo[r][1] = lds32(Al, row + 8, w);
                alo[r][2] = lds32(Al, row,     w + 4);
                alo[r][3] = lds32(Al, row + 8, w + 4);
            }
            #pragma unroll
            for (int j = 0; j < 8; j++) {
                int n = warpN * 64 + j * 8 + rA;
                uint32_t bh0 = lds32(Wh, n, w);
                uint32_t bh1 = lds32(Wh, n, w + 4);
                uint32_t bl0 = lds32(Wl, n, w);
                uint32_t bl1 = lds32(Wl, n, w + 4);
                #pragma unroll
                for (int r = 0; r < 2; r++) {
                    mma_bf16(acc[r][j], ahi[r], bh0, bh1);
                    mma_bf16(acc[r][j], ahi[r], bl0, bl1);
                    mma_bf16(acc[r][j], alo[r], bh0, bh1);
                }
            }
        }

        if (i < 31) {
            uint32_t off = (uint32_t)ldRow * ROWB + ldC4 * 8;
            const int ns = (i + 1) & 1;
            #pragma unroll
            for (int it = 0; it < 4; it++) {
                split_store(TILE_PTR(ns,0), TILE_PTR(ns,1), off + it * 32 * ROWB, aV[it]);
                split_store(TILE_PTR(ns,2), TILE_PTR(ns,3), off + it * 32 * ROWB, wV[it]);
            }
            __syncthreads();
        }
    }

    #pragma unroll
    for (int r = 0; r < 2; r++) {
        #pragma unroll
        for (int half = 0; half < 2; half++) {
            const int m = m0 + warpM * 32 + r * 16 + rA + half * 8;
            const int sIdx = m & (SS - 1);
            const int s1 = sIdx >> 6;
            const int s0 = sIdx & 63;
            float* orow = OUT + (size_t)m * HH;
            #pragma unroll
            for (int j = 0; j < 8; j++) {
                const int h = warpN * 64 + j * 8 + wBase * 2;
                float x0 = acc[r][j][half * 2 + 0] + s_bias[h];
                float x1 = acc[r][j][half * 2 + 1] + s_bias[h + 1];
                if (z == 2) {
                    *(float2*)&orow[h] = make_float2(x0, x1);
                } else {
                    const int d = h >> 1;
                    float4 A4 = g_tabA[d][s1];
                    float4 B4 = g_tabB[d][s0];
                    float sn = A4.x * B4.y + A4.y * B4.x;
                    float cs = A4.y * B4.y - A4.x * B4.x;
                    float sc = (z == 0) ? A4.z * B4.z : A4.w * B4.w;
                    sn *= sc; cs *= sc;
                    *(float2*)&orow[h] = make_float2(x0 * cs - x1 * sn, x1 * cs + x0 * sn);
                }
            }
        }
    }
    #undef TILE_PTR
}

// ==================== shared tile constants for retention kernels ====================
#define RS 272                      // 128 bf16 * 2 + 16 pad (16B-divisible: uint4-safe)
#define TB (128*RS)                 // 34816 B per tile
#define CHUNK_SMEM (4*TB + 512)
#define INTRA_SMEM (6*TB + 1024)

// row-major load+split: src rows [r][h] fp32 -> buf hi/lo bf16 (optional per-row scale)
__device__ __forceinline__ void load_split_rows(const float* src, char* bh, char* bl,
                                                int tid, const float* rowScale) {
    #pragma unroll
    for (int it = 0; it < 16; it++) {
        int idx = it * 256 + tid;
        int row = idx >> 5;
        int c4  = idx & 31;
        float4 v = *(const float4*)&src[(size_t)row * HH + c4 * 4];
        if (rowScale) {
            float s = rowScale[row];
            v.x *= s; v.y *= s; v.z *= s; v.w *= s;
        }
        split_store(bh, bl, (uint32_t)row * RS + c4 * 8, v);
    }
}

// transpose load+split: src rows [j][h] fp32 -> buf [h][j] bf16 hi/lo (optional per-j scale)
__device__ __forceinline__ void load_split_trans(const float* src, char* bh, char* bl,
                                                 int tid, const float* jScale) {
    #pragma unroll
    for (int it = 0; it < 16; it++) {
        int idx = it * 256 + tid;
        int j  = idx >> 5;
        int h4 = idx & 31;
        float4 v = *(const float4*)&src[(size_t)j * HH + h4 * 4];
        if (jScale) {
            float s = jScale[j];
            v.x *= s; v.y *= s; v.z *= s; v.w *= s;
        }
        float vv[4] = {v.x, v.y, v.z, v.w};
        #pragma unroll
        for (int e = 0; e < 4; e++) {
            __nv_bfloat16 h, l;
            split1(vv[e], h, l);
            int h2 = h4 * 4 + e;
            *(__nv_bfloat16*)(bh + (uint32_t)h2 * RS + j * 2) = h;
            *(__nv_bfloat16*)(bl + (uint32_t)h2 * RS + j * 2) = l;
        }
    }
}

// ==================== chunk summary: T_c[h2][h1] = sum_j V[j,h2] * gamma^(C-1-j) K[j,h1] ====================
__global__ __launch_bounds__(256, 1)
void chunk_t_kernel()
{
    extern __shared__ char sm[];
    char* Vth = sm;
    char* Vtl = sm + TB;
    char* Kth = sm + 2*TB;
    char* Ktl = sm + 3*TB;
    float* gpos = (float*)(sm + 4*TB);     // gamma^t, t=0..127

    const int bc = blockIdx.x;
    const int b = bc >> 5;
    const int c = bc & 31;
    const float* Kp = g_K + (size_t)(b * SS + c * CC) * HH;
    const float* Vp = g_V + (size_t)(b * SS + c * CC) * HH;
    float* Tp = g_A + (size_t)bc * HH * HH;

    const int tid = threadIdx.x;
    const int wid = tid >> 5;
    const int lane = tid & 31;
    const int rA = lane >> 2;
    const int wq = lane & 3;

    if (tid < 128) gpos[tid] = exp2f((float)tid * LG2G);
    __syncthreads();

    __shared__ float kScale[128];
    if (tid < 128) kScale[tid] = gpos[127 - tid];
    __syncthreads();

    load_split_trans(Vp, Vth, Vtl, tid, nullptr);   // Vt[h2][j]
    load_split_trans(Kp, Kth, Ktl, tid, kScale);    // gKt[h1][j]
    __syncthreads();

    const int m0 = wid * 16;    // h2 rows
    float acc[16][4];
    #pragma unroll
    for (int n8 = 0; n8 < 16; n8++)
        #pragma unroll
        for (int cc = 0; cc < 4; cc++) acc[n8][cc] = 0.f;

    #pragma unroll
    for (int kk = 0; kk < 8; kk++) {
        const uint32_t kb = kk * 32 + wq * 4;
        uint32_t ah[4], al[4];
        ah[0] = *(uint32_t*)(Vth + (m0 + rA) * RS + kb);
        ah[1] = *(uint32_t*)(Vth + (m0 + rA + 8) * RS + kb);
        ah[2] = *(uint32_t*)(Vth + (m0 + rA) * RS + kb + 16);
        ah[3] = *(uint32_t*)(Vth + (m0 + rA + 8) * RS + kb + 16);
        al[0] = *(uint32_t*)(Vtl + (m0 + rA) * RS + kb);
        al[1] = *(uint32_t*)(Vtl + (m0 + rA + 8) * RS + kb);
        al[2] = *(uint32_t*)(Vtl + (m0 + rA) * RS + kb + 16);
        al[3] = *(uint32_t*)(Vtl + (m0 + rA + 8) * RS + kb + 16);
        #pragma unroll
        for (int n8 = 0; n8 < 16; n8++) {
            uint32_t bh0 = *(uint32_t*)(Kth + (n8 * 8 + rA) * RS + kb);
            uint32_t bh1 = *(uint32_t*)(Kth + (n8 * 8 + rA) * RS + kb + 16);
            uint32_t bl0 = *(uint32_t*)(Ktl + (n8 * 8 + rA) * RS + kb);
            uint32_t bl1 = *(uint32_t*)(Ktl + (n8 * 8 + rA) * RS + kb + 16);
            mma_bf16(acc[n8], ah, bh0, bh1);
            mma_bf16(acc[n8], ah, bl0, bl1);
            mma_bf16(acc[n8], al, bh0, bh1);
        }
    }

    #pragma unroll
    for (int n8 = 0; n8 < 16; n8++) {
        int h1 = n8 * 8 + wq * 2;
        *(float2*)&Tp[(size_t)(m0 + rA) * HH + h1]     = make_float2(acc[n8][0], acc[n8][1]);
        *(float2*)&Tp[(size_t)(m0 + rA + 8) * HH + h1] = make_float2(acc[n8][2], acc[n8][3]);
    }
}

// ==================== prefix scan: states, split bf16 output ====================
__global__ void scan_kernel()
{
    int e = blockIdx.x * 256 + threadIdx.x;
    int b = e >> 14;
    int off = e & 16383;
    float st = 0.f;
    const float dC = exp2f((float)CC * LG2G);
    for (int c = 0; c < NCHUNK; c++) {
        size_t idx = (((size_t)(b * NCHUNK + c)) << 14) + off;
        __nv_bfloat16 h, l;
        split1(st, h, l);
        g_Sth[idx] = h;
        g_Stl[idx] = l;
        st = st * dC + g_A[idx];
    }
}

// ==================== intra + cross output ====================
__global__ __launch_bounds__(256, 1)
void intra_kernel(float* __restrict__ out)
{
    extern __shared__ char sm[];
    char* Qh = sm;
    char* Ql = sm + TB;
    char* Xh = sm + 2*TB;       // K rows -> Vt -> Stt
    char* Xl = sm + 3*TB;
    char* Wh = sm + 4*TB;       // Qw = gamma^(i+1) * Q
    char* Wl = sm + 5*TB;
    float* gpos = (float*)(sm + 6*TB);          // gamma^t
    float* gneg = gpos + 128;                   // gamma^-t
    __shared__ float qScale[128];

    const int bc = blockIdx.x;
    const int b = bc >> 5;
    const int c = bc & 31;
    const float* Qp = g_Q + (size_t)(b * SS + c * CC) * HH;
    const float* Kp = g_K + (size_t)(b * SS + c * CC) * HH;
    const float* Vp = g_V + (size_t)(b * SS + c * CC) * HH;

    const int tid = threadIdx.x;
    const int wid = tid >> 5;
    const int lane = tid & 31;
    const int rA = lane >> 2;
    const int wq = lane & 3;
    const int i0 = wid * 16;

    if (tid < 128) {
        gpos[tid] = exp2f((float)tid * LG2G);
        gneg[tid] = exp2f(-(float)tid * LG2G);
        qScale[tid] = exp2f((float)(tid + 1) * LG2G);
    }
    __syncthreads();

    load_split_rows(Qp, Qh, Ql, tid, nullptr);
    load_split_rows(Qp, Wh, Wl, tid, qScale);
    load_split_rows(Kp, Xh, Xl, tid, nullptr);
    __syncthreads();

    // ---- Phase 1: S = Q K^T ----
    float acc[16][4];
    #pragma unroll
    for (int n8 = 0; n8 < 16; n8++)
        #pragma unroll
        for (int cc = 0; cc < 4; cc++) acc[n8][cc] = 0.f;

    #pragma unroll
    for (int kk = 0; kk < 8; kk++) {
        const uint32_t kb = kk * 32 + wq * 4;
        uint32_t ah[4], al[4];
        ah[0] = *(uint32_t*)(Qh + (i0 + rA) * RS + kb);
        ah[1] = *(uint32_t*)(Qh + (i0 + rA + 8) * RS + kb);
        ah[2] = *(uint32_t*)(Qh + (i0 + rA) * RS + kb + 16);
        ah[3] = *(uint32_t*)(Qh + (i0 + rA + 8) * RS + kb + 16);
        al[0] = *(uint32_t*)(Ql + (i0 + rA) * RS + kb);
        al[1] = *(uint32_t*)(Ql + (i0 + rA + 8) * RS + kb);
        al[2] = *(uint32_t*)(Ql + (i0 + rA) * RS + kb + 16);
        al[3] = *(uint32_t*)(Ql + (i0 + rA + 8) * RS + kb + 16);
        #pragma unroll
        for (int n8 = 0; n8 < 16; n8++) {
            uint32_t bh0 = *(uint32_t*)(Xh + (n8 * 8 + rA) * RS + kb);
            uint32_t bh1 = *(uint32_t*)(Xh + (n8 * 8 + rA) * RS + kb + 16);
            uint32_t bl0 = *(uint32_t*)(Xl + (n8 * 8 + rA) * RS + kb);
            uint32_t bl1 = *(uint32_t*)(Xl + (n8 * 8 + rA) * RS + kb + 16);
            mma_bf16(acc[n8], ah, bh0, bh1);
            mma_bf16(acc[n8], ah, bl0, bl1);
            mma_bf16(acc[n8], al, bh0, bh1);
        }
    }

    // ---- mask + decay, repack C-frags -> A-frags (hi/lo) in registers ----
    const int iLo = i0 + rA;
    const int iHi = iLo + 8;
    const float gLo = gpos[iLo];
    const float gHi = gpos[iHi];
    uint32_t sFh[8][4], sFl[8][4];
    #pragma unroll
    for (int n8 = 0; n8 < 16; n8++) {
        int j0 = n8 * 8 + 2 * wq;
        int j1 = j0 + 1;
        float gn0 = gneg[j0], gn1 = gneg[j1];
        float s0 = (j0 <= iLo) ? acc[n8][0] * (gLo * gn0) : 0.f;
        float s1 = (j1 <= iLo) ? acc[n8][1] * (gLo * gn1) : 0.f;
        float s2 = (j0 <= iHi) ? acc[n8][2] * (gHi * gn0) : 0.f;
        float s3 = (j1 <= iHi) ? acc[n8][3] * (gHi * gn1) : 0.f;
        uint32_t h01 = pack_bf16x2(s0, s1);
        uint32_t h23 = pack_bf16x2(s2, s3);
        float l0 = s0 - __uint_as_float(h01 << 16);
        float l1 = s1 - __uint_as_float(h01 & 0xFFFF0000u);
        float l2 = s2 - __uint_as_float(h23 << 16);
        float l3 = s3 - __uint_as_float(h23 & 0xFFFF0000u);
        int kk2 = n8 >> 1;
        int half = (n8 & 1) * 2;
        sFh[kk2][half + 0] = h01;
        sFh[kk2][half + 1] = h23;
        sFl[kk2][half + 0] = pack_bf16x2(l0, l1);
        sFl[kk2][half + 1] = pack_bf16x2(l2, l3);
    }
    __syncthreads();

    // ---- load Vt into X buffer ----
    load_split_trans(Vp, Xh, Xl, tid, nullptr);
    __syncthreads();

    // ---- Phase 3a: O = S @ V  (A = S frags, B = Vt) ----
    #pragma unroll
    for (int n8 = 0; n8 < 16; n8++)
        #pragma unroll
        for (int cc = 0; cc < 4; cc++) acc[n8][cc] = 0.f;

    #pragma unroll
    for (int kk = 0; kk < 8; kk++) {
        const uint32_t kb = kk * 32 + wq * 4;
        #pragma unroll
        for (int n8 = 0; n8 < 16; n8++) {
            uint32_t bh0 = *(uint32_t*)(Xh + (n8 * 8 + rA) * RS + kb);
            uint32_t bh1 = *(uint32_t*)(Xh + (n8 * 8 + rA) * RS + kb + 16);
            uint32_t bl0 = *(uint32_t*)(Xl + (n8 * 8 + rA) * RS + kb);
            uint32_t bl1 = *(uint32_t*)(Xl + (n8 * 8 + rA) * RS + kb + 16);
            mma_bf16(acc[n8], sFh[kk], bh0, bh1);
            mma_bf16(acc[n8], sFh[kk], bl0, bl1);
            mma_bf16(acc[n8], sFl[kk], bh0, bh1);
        }
    }
    __syncthreads();

    // ---- load Stt (bf16, pre-split) into X buffer ----
    {
        const __nv_bfloat16* Sh = g_Sth + (size_t)bc * HH * HH;
        const __nv_bfloat16* Sl = g_Stl + (size_t)bc * HH * HH;
        #pragma unroll
        for (int it = 0; it < 8; it++) {
            int idx = it * 256 + tid;
            int row = idx >> 4;
            int qv  = idx & 15;
            *(uint4*)(Xh + (uint32_t)row * RS + qv * 16) = *(const uint4*)(Sh + (size_t)row * HH + qv * 8);
            *(uint4*)(Xl + (uint32_t)row * RS + qv * 16) = *(const uint4*)(Sl + (size_t)row * HH + qv * 8);
        }
    }
    __syncthreads();

    // ---- Phase 3b: O += (gamma^(i+1) Q) @ St  (A = Qw, B = Stt) ----
    #pragma unroll
    for (int kk = 0; kk < 8; kk++) {
        const uint32_t kb = kk * 32 + wq * 4;
        uint32_t ah[4], al[4];
        ah[0] = *(uint32_t*)(Wh + (i0 + rA) * RS + kb);
        ah[1] = *(uint32_t*)(Wh + (i0 + rA + 8) * RS + kb);
        ah[2] = *(uint32_t*)(Wh + (i0 + rA) * RS + kb + 16);
        ah[3] = *(uint32_t*)(Wh + (i0 + rA + 8) * RS + kb + 16);
        al[0] = *(uint32_t*)(Wl + (i0 + rA) * RS + kb);
        al[1] = *(uint32_t*)(Wl + (i0 + rA + 8) * RS + kb);
        al[2] = *(uint32_t*)(Wl + (i0 + rA) * RS + kb + 16);
        al[3] = *(uint32_t*)(Wl + (i0 + rA + 8) * RS + kb + 16);
        #pragma unroll
        for (int n8 = 0; n8 < 16; n8++) {
            uint32_t bh0 = *(uint32_t*)(Xh + (n8 * 8 + rA) * RS + kb);
            uint32_t bh1 = *(uint32_t*)(Xh + (n8 * 8 + rA) * RS + kb + 16);
            uint32_t bl0 = *(uint32_t*)(Xl + (n8 * 8 + rA) * RS + kb);
            uint32_t bl1 = *(uint32_t*)(Xl + (n8 * 8 + rA) * RS + kb + 16);
            mma_bf16(acc[n8], ah, bh0, bh1);
            mma_bf16(acc[n8], ah, bl0, bl1);
            mma_bf16(acc[n8], al, bh0, bh1);
        }
    }

    // ---- store O ----
    float* obase = out + (size_t)(b * SS + c * CC) * HH;
    #pragma unroll
    for (int n8 = 0; n8 < 16; n8++) {
        int h2 = n8 * 8 + wq * 2;
        *(float2*)&obase[(size_t)(i0 + rA) * HH + h2]     = make_float2(acc[n8][0], acc[n8][1]);
        *(float2*)&obase[(size_t)(i0 + rA + 8) * HH + h2] = make_float2(acc[n8][2], acc[n8][3]);
    }
}

// ====================================================================
extern "C" void kernel_launch(void* const* d_in, const int* in_sizes, int n_in,
                              void* d_out, int out_size)
{
    const float* q  = (const float*)d_in[0];
    const float* k  = (const float*)d_in[1];
    const float* v  = (const float*)d_in[2];
    const float* Wq = (const float*)d_in[3];
    const float* bq = (const float*)d_in[4];
    const float* Wk = (const float*)d_in[5];
    const float* bk = (const float*)d_in[6];
    const float* Wv = (const float*)d_in[7];
    const float* bv = (const float*)d_in[8];
    float* out = (float*)d_out;

    cudaFuncSetAttribute(proj_mma_kernel, cudaFuncAttributeMaxDynamicSharedMemorySize, PROJ_SMEM);
    cudaFuncSetAttribute(chunk_t_kernel, cudaFuncAttributeMaxDynamicSharedMemorySize, CHUNK_SMEM);
    cudaFuncSetAttribute(intra_kernel, cudaFuncAttributeMaxDynamicSharedMemorySize, INTRA_SMEM);

    build_tab_kernel<<<32, 256>>>();

    dim3 gproj(128, 3, 1);
    proj_mma_kernel<<<gproj, 256, PROJ_SMEM>>>(q, k, v, Wq, bq, Wk, bk, Wv, bv);

    chunk_t_kernel<<<BB * NCHUNK, 256, CHUNK_SMEM>>>();
    scan_kernel<<<(BB * HH * HH) / 256, 256>>>();
    intra_kernel<<<BB * NCHUNK, 256, INTRA_SMEM>>>(out);
}